// round 8
// baseline (speedup 1.0000x reference)
#include <cuda_runtime.h>
#include <cuda_fp16.h>
#include <cstdint>

// ---------------- problem constants ----------------
constexpr int cN = 100000;   // nodes
constexpr int cE = 1600000;  // edges
constexpr int cD = 128;      // feature dim
constexpr int cK = 4;        // etypes
constexpr int cM = cK * cN;                  // 400000 keys (dst*4+etype)
constexpr int SCAN_NB = (cM + 1023) / 1024;  // 391

// ---------------- scratch ----------------
__device__ __align__(16) float g_h0[(size_t)cN * cD];
__device__ __align__(16) float g_h1[(size_t)cN * cD];
__device__ __align__(16) float g_a[(size_t)cN * cD];
__device__ __align__(16) float g_bsum[(size_t)cN * cD];

__device__ int g_deg[cM];
__device__ int g_rp[cM + 1];
__device__ int g_cur[cM];
__device__ int g_esrc[cE];
__device__ int g_part[512];

// ---------------- helpers ----------------
__device__ __forceinline__ float sigmf(float x) { return 1.0f / (1.0f + __expf(-x)); }

__device__ __forceinline__ uint32_t pk2(float x, float y) {
    __half2 h = __floats2half2_rn(x, y);
    return *reinterpret_cast<uint32_t*>(&h);
}

__device__ __forceinline__ void mma_f16(float c[4], const uint32_t a[4], const uint32_t b[2]) {
    asm volatile(
        "mma.sync.aligned.m16n8k16.row.col.f32.f16.f16.f32 "
        "{%0,%1,%2,%3}, {%4,%5,%6,%7}, {%8,%9}, {%0,%1,%2,%3};"
        : "+f"(c[0]), "+f"(c[1]), "+f"(c[2]), "+f"(c[3])
        : "r"(a[0]), "r"(a[1]), "r"(a[2]), "r"(a[3]), "r"(b[0]), "r"(b[1]));
}

// ---------------- CSR build ----------------
__global__ void k_fill_deg() {
    int i = blockIdx.x * blockDim.x + threadIdx.x;
    if (i < cM) g_deg[i] = 0;
}
__global__ void k_hist(const int* __restrict__ dst, const int* __restrict__ et) {
    int e = blockIdx.x * blockDim.x + threadIdx.x;
    if (e < cE) atomicAdd(&g_deg[dst[e] * 4 + et[e]], 1);
}
__global__ void k_scan1() {
    __shared__ int sm[1024];
    int i = blockIdx.x * 1024 + threadIdx.x;
    int v = (i < cM) ? g_deg[i] : 0;
    sm[threadIdx.x] = v;
    __syncthreads();
    for (int off = 1; off < 1024; off <<= 1) {
        int t = 0;
        if (threadIdx.x >= off) t = sm[threadIdx.x - off];
        __syncthreads();
        sm[threadIdx.x] += t;
        __syncthreads();
    }
    if (i < cM) g_rp[i] = sm[threadIdx.x] - v;
    if (threadIdx.x == 1023) g_part[blockIdx.x] = sm[1023];
}
__global__ void k_scan2() {
    __shared__ int sm[512];
    int t = threadIdx.x;
    int v = (t < SCAN_NB) ? g_part[t] : 0;
    sm[t] = v;
    __syncthreads();
    for (int off = 1; off < 512; off <<= 1) {
        int x = 0;
        if (t >= off) x = sm[t - off];
        __syncthreads();
        sm[t] += x;
        __syncthreads();
    }
    if (t < SCAN_NB) g_part[t] = sm[t] - v;
    if (t == 511) g_rp[cM] = sm[511];
}
__global__ void k_scan3() {  // also initializes g_cur
    int i = blockIdx.x * 1024 + threadIdx.x;
    if (i < cM) {
        int v = g_rp[i] + g_part[blockIdx.x];
        g_rp[i] = v;
        g_cur[i] = v;
    }
}
__global__ void k_scatter(const int* __restrict__ src, const int* __restrict__ dst,
                          const int* __restrict__ et) {
    int e = blockIdx.x * blockDim.x + threadIdx.x;
    if (e < cE) {
        int key = dst[e] * 4 + et[e];
        int pos = atomicAdd(&g_cur[key], 1);
        g_esrc[pos] = src[e];
    }
}
__global__ void k_bsum(const float* __restrict__ bet) {
    int idx = blockIdx.x * blockDim.x + threadIdx.x;
    if (idx >= cN * cD) return;
    int r = idx >> 7, col = idx & 127;
    int rp[5];
#pragma unroll
    for (int k = 0; k <= 4; k++) rp[k] = g_rp[4 * r + k];
    float v = 0.f;
#pragma unroll
    for (int k = 0; k < 4; k++) v += (float)(rp[k + 1] - rp[k]) * __ldg(&bet[k * cD + col]);
    g_bsum[idx] = v;
}

// ---------------- fp16 GEMM building blocks ----------------
constexpr int LD2 = 136;  // halves per smem row (272B stride, conflict-free)

__device__ __forceinline__ void load_tile_X16(const float* __restrict__ X, __half* Xs,
                                              int rowBase, int nrows, int tid) {
    for (int idx = tid; idx < 128 * 32; idx += 256) {
        int row = idx >> 5, c4 = (idx & 31) * 4;
        float4 v = make_float4(0.f, 0.f, 0.f, 0.f);
        int r = rowBase + row;
        if (r < nrows) v = *reinterpret_cast<const float4*>(X + (size_t)r * cD + c4);
        *reinterpret_cast<uint2*>(Xs + row * LD2 + c4) = make_uint2(pk2(v.x, v.y), pk2(v.z, v.w));
    }
}
__device__ __forceinline__ void load_tile_W64_16(const float* __restrict__ W, int ldw, __half* Ws,
                                                 int colBase, int tid) {
    for (int idx = tid; idx < 64 * 32; idx += 256) {
        int o = idx >> 5, c4 = (idx & 31) * 4;
        float4 v = *reinterpret_cast<const float4*>(W + (size_t)(colBase + o) * ldw + c4);
        *reinterpret_cast<uint2*>(Ws + o * LD2 + c4) = make_uint2(pk2(v.x, v.y), pk2(v.z, v.w));
    }
}
__device__ __forceinline__ void load_tile_W128_16(const float* __restrict__ W, int ldw, __half* Ws,
                                                  int tid) {
    for (int idx = tid; idx < 128 * 32; idx += 256) {
        int o = idx >> 5, c4 = (idx & 31) * 4;
        float4 v = *reinterpret_cast<const float4*>(W + (size_t)o * ldw + c4);
        *reinterpret_cast<uint2*>(Ws + o * LD2 + c4) = make_uint2(pk2(v.x, v.y), pk2(v.z, v.w));
    }
}
__device__ __forceinline__ uint32_t lds32(const __half* p) {
    return *reinterpret_cast<const uint32_t*>(p);
}

// warp-tile 32x32 mainloop, fp16 k16
__device__ __forceinline__ void mma_loop32(const __half* Xs, const __half* Ws,
                                           int wm, int wn, int gr, int gc, float c[2][4][4]) {
#pragma unroll
    for (int k0 = 0; k0 < cD; k0 += 16) {
        uint32_t a[2][4], b[4][2];
#pragma unroll
        for (int i = 0; i < 2; i++) {
            const __half* base = Xs + (wm + i * 16 + gr) * LD2 + k0 + 2 * gc;
            a[i][0] = lds32(base);
            a[i][1] = lds32(base + 8 * LD2);
            a[i][2] = lds32(base + 8);
            a[i][3] = lds32(base + 8 * LD2 + 8);
        }
#pragma unroll
        for (int j = 0; j < 4; j++) {
            const __half* base = Ws + (wn + j * 8 + gr) * LD2 + k0 + 2 * gc;
            b[j][0] = lds32(base);
            b[j][1] = lds32(base + 8);
        }
#pragma unroll
        for (int i = 0; i < 2; i++)
#pragma unroll
            for (int j = 0; j < 4; j++) mma_f16(c[i][j], a[i], b[j]);
    }
}
// warp-tile 32x64 mainloop, fp16 k16
__device__ __forceinline__ void mma_loop64(const __half* Xs, const __half* Ws,
                                           int wm, int wn, int gr, int gc, float c[2][8][4]) {
#pragma unroll
    for (int k0 = 0; k0 < cD; k0 += 16) {
        uint32_t a[2][4], b[8][2];
#pragma unroll
        for (int i = 0; i < 2; i++) {
            const __half* base = Xs + (wm + i * 16 + gr) * LD2 + k0 + 2 * gc;
            a[i][0] = lds32(base);
            a[i][1] = lds32(base + 8 * LD2);
            a[i][2] = lds32(base + 8);
            a[i][3] = lds32(base + 8 * LD2 + 8);
        }
#pragma unroll
        for (int j = 0; j < 8; j++) {
            const __half* base = Ws + (wn + j * 8 + gr) * LD2 + k0 + 2 * gc;
            b[j][0] = lds32(base);
            b[j][1] = lds32(base + 8);
        }
#pragma unroll
        for (int i = 0; i < 2; i++)
#pragma unroll
            for (int j = 0; j < 8; j++) mma_f16(c[i][j], a[i], b[j]);
    }
}

// ---------------- fused aggregation + etype GEMM (128-row blocks, 32x64 warp tiles) ----------------
constexpr int SM_AE = (128 + 128) * LD2 * 2;  // 69632 -> 3 CTAs/SM

__global__ __launch_bounds__(256, 3) void k_agg_etype(const float* __restrict__ h,
                                                      const float* __restrict__ Wet) {
    extern __shared__ __half smh[];
    __half* Xs = smh;              // 128 x LD2
    __half* Ws = smh + 128 * LD2;  // 128 x LD2
    int tid = threadIdx.x, lane = tid & 31, warp = tid >> 5;
    int rowBase = blockIdx.x * 128;
    int wm = (warp & 3) * 32, wn = (warp >> 2) * 64;
    int gr = lane >> 2, gc = lane & 3;
    const float4* hp = reinterpret_cast<const float4*>(h);

    float c[2][8][4];
#pragma unroll
    for (int i = 0; i < 2; i++)
#pragma unroll
        for (int j = 0; j < 8; j++)
#pragma unroll
            for (int q = 0; q < 4; q++) c[i][j][q] = 0.f;

    for (int ke = 0; ke < cK; ke++) {
        if (ke) __syncthreads();  // previous mma done reading Xs/Ws
        // ---- aggregate: 16 nodes per warp, lane covers 4 feature cols ----
#pragma unroll
        for (int i = 0; i < 16; i++) {
            int vl = warp * 16 + i;
            int v = rowBase + vl;
            float4 acc = make_float4(0.f, 0.f, 0.f, 0.f);
            if (v < cN) {
                int r0 = __ldg(&g_rp[4 * v + ke]), r1 = __ldg(&g_rp[4 * v + ke + 1]);
                int e = r0;
                for (; e + 4 <= r1; e += 4) {  // MLP-4 gather
                    int s0 = __ldg(&g_esrc[e]), s1 = __ldg(&g_esrc[e + 1]);
                    int s2 = __ldg(&g_esrc[e + 2]), s3 = __ldg(&g_esrc[e + 3]);
                    float4 x0 = hp[(size_t)s0 * 32 + lane];
                    float4 x1 = hp[(size_t)s1 * 32 + lane];
                    float4 x2 = hp[(size_t)s2 * 32 + lane];
                    float4 x3 = hp[(size_t)s3 * 32 + lane];
                    acc.x += (x0.x + x1.x) + (x2.x + x3.x);
                    acc.y += (x0.y + x1.y) + (x2.y + x3.y);
                    acc.z += (x0.z + x1.z) + (x2.z + x3.z);
                    acc.w += (x0.w + x1.w) + (x2.w + x3.w);
                }
                for (; e < r1; e++) {
                    int s = __ldg(&g_esrc[e]);
                    float4 x = hp[(size_t)s * 32 + lane];
                    acc.x += x.x; acc.y += x.y; acc.z += x.z; acc.w += x.w;
                }
            }
            *reinterpret_cast<uint2*>(Xs + vl * LD2 + lane * 4) =
                make_uint2(pk2(acc.x, acc.y), pk2(acc.z, acc.w));
        }
        load_tile_W128_16(Wet + (size_t)ke * cD * cD, cD, Ws, tid);
        __syncthreads();
        mma_loop64(Xs, Ws, wm, wn, gr, gc, c);
    }

#pragma unroll
    for (int i = 0; i < 2; i++)
#pragma unroll
        for (int j = 0; j < 8; j++) {
            int col = wn + j * 8 + 2 * gc;
#pragma unroll
            for (int half = 0; half < 2; half++) {
                int r = rowBase + wm + i * 16 + gr + half * 8;
                if (r >= cN) continue;
                float2 bs = *reinterpret_cast<const float2*>(g_bsum + (size_t)r * cD + col);
                float2 o = make_float2(c[i][j][half * 2] + bs.x, c[i][j][half * 2 + 1] + bs.y);
                *reinterpret_cast<float2*>(g_a + (size_t)r * cD + col) = o;
            }
        }
}

// ---------------- fused GRU: one block = 128 rows, both 64-col halves, W double-buffered ----------------
constexpr int SM_GRU = (2 * 128 + 2 * 64) * LD2 * 2;  // 104448 -> 2 CTAs/SM

__global__ __launch_bounds__(256, 2) void k_gru_fused(
    const float* __restrict__ A, const float* __restrict__ H,
    const float* __restrict__ W_ih, const float* __restrict__ b_ih,
    const float* __restrict__ W_hh, const float* __restrict__ b_hh,
    float* __restrict__ hout) {
    extern __shared__ __half smh[];
    __half* Xa = smh;
    __half* Xh = smh + 128 * LD2;
    __half* Wb[2] = {smh + 256 * LD2, smh + 320 * LD2};
    int tid = threadIdx.x;
    int rowBase = blockIdx.x * 128;
    int lane = tid & 31, warp = tid >> 5;
    int wm = (warp & 3) * 32, wn = (warp >> 2) * 32;
    int gr = lane >> 2, gc = lane & 3;

    load_tile_X16(A, Xa, rowBase, cN, tid);
    load_tile_X16(H, Xh, rowBase, cN, tid);

    // W tile schedule: t = cb*6 + g*2 + part   (cb: col half, g: gate, part: ih/hh)
    auto loadW = [&](int t, __half* buf) {
        int cb = (t >= 6) ? 64 : 0;
        int u = t % 6, g = u >> 1, part = u & 1;
        const float* Wp = (part ? W_hh : W_ih) + (size_t)g * 128 * cD;
        load_tile_W64_16(Wp, cD, buf, cb, tid);
    };
    loadW(0, Wb[0]);

    float rf[2][4][4], zf[2][4][4], ci[2][4][4], ch[2][4][4];

#pragma unroll 1
    for (int t = 0; t < 12; t++) {
        __syncthreads();  // tile t staged; mma(t-1) complete (buffer safe to overwrite)
        if (t + 1 < 12) loadW(t + 1, Wb[(t + 1) & 1]);  // overlap with mma below
        int u = t % 6, g = u >> 1, part = u & 1;
        int colBase = (t >= 6) ? 64 : 0;
        float (*acc)[4][4] = part ? ch : ci;
#pragma unroll
        for (int i = 0; i < 2; i++)
#pragma unroll
            for (int j = 0; j < 4; j++)
#pragma unroll
                for (int q = 0; q < 4; q++) acc[i][j][q] = 0.f;
        mma_loop32(part ? Xh : Xa, Wb[t & 1], wm, wn, gr, gc, acc);

        if (part == 1) {  // gate epilogue (registers only)
#pragma unroll
            for (int i = 0; i < 2; i++)
#pragma unroll
                for (int j = 0; j < 4; j++) {
                    int col = colBase + wn + j * 8 + 2 * gc;
                    float bi0 = __ldg(&b_ih[g * 128 + col]), bi1 = __ldg(&b_ih[g * 128 + col + 1]);
                    float bh0 = __ldg(&b_hh[g * 128 + col]), bh1 = __ldg(&b_hh[g * 128 + col + 1]);
                    if (g == 0) {
#pragma unroll
                        for (int q = 0; q < 4; q++) {
                            float bi = (q & 1) ? bi1 : bi0, bh = (q & 1) ? bh1 : bh0;
                            rf[i][j][q] = sigmf(ci[i][j][q] + bi + ch[i][j][q] + bh);
                        }
                    } else if (g == 1) {
#pragma unroll
                        for (int q = 0; q < 4; q++) {
                            float bi = (q & 1) ? bi1 : bi0, bh = (q & 1) ? bh1 : bh0;
                            zf[i][j][q] = sigmf(ci[i][j][q] + bi + ch[i][j][q] + bh);
                        }
                    } else {
#pragma unroll
                        for (int half = 0; half < 2; half++) {
                            int r = rowBase + wm + i * 16 + gr + half * 8;
                            if (r >= cN) continue;
                            float2 hv = *reinterpret_cast<const float2*>(H + (size_t)r * cD + col);
                            int q0 = half * 2, q1 = half * 2 + 1;
                            float n0 = tanhf(ci[i][j][q0] + bi0 + rf[i][j][q0] * (ch[i][j][q0] + bh0));
                            float n1 = tanhf(ci[i][j][q1] + bi1 + rf[i][j][q1] * (ch[i][j][q1] + bh1));
                            float2 o;
                            o.x = (1.0f - zf[i][j][q0]) * n0 + zf[i][j][q0] * hv.x;
                            o.y = (1.0f - zf[i][j][q1]) * n1 + zf[i][j][q1] * hv.y;
                            *reinterpret_cast<float2*>(hout + (size_t)r * cD + col) = o;
                        }
                    }
                }
        }
    }
}

// ---------------- fused output head ----------------
constexpr int SM_HEAD = 3 * 128 * LD2 * 2;  // 104448 -> 2 CTAs/SM

__global__ __launch_bounds__(256, 2) void k_head(
    const float* __restrict__ H, const float* __restrict__ F,
    const float* __restrict__ i_w, const float* __restrict__ i_b,
    const float* __restrict__ j_w, const float* __restrict__ j_b,
    float* __restrict__ out) {
    extern __shared__ __half smh[];
    __half* Xh = smh;
    __half* Xf = smh + 128 * LD2;
    __half* Ws = smh + 256 * LD2;
    int tid = threadIdx.x;
    int rowBase = blockIdx.x * 128;
    int lane = tid & 31, warp = tid >> 5;
    int wm = (warp & 3) * 32, wn = (warp >> 2) * 64;
    int gr = lane >> 2, gc = lane & 3;

    load_tile_X16(H, Xh, rowBase, cN, tid);
    load_tile_X16(F, Xf, rowBase, cN, tid);

    float cg[2][8][4], cj[2][8][4];
#pragma unroll
    for (int i = 0; i < 2; i++)
#pragma unroll
        for (int j = 0; j < 8; j++)
#pragma unroll
            for (int q = 0; q < 4; q++) { cg[i][j][q] = 0.f; cj[i][j][q] = 0.f; }

    load_tile_W128_16(i_w, 2 * cD, Ws, tid);
    __syncthreads();
    mma_loop64(Xh, Ws, wm, wn, gr, gc, cg);
    __syncthreads();
    load_tile_W128_16(i_w + cD, 2 * cD, Ws, tid);
    __syncthreads();
    mma_loop64(Xf, Ws, wm, wn, gr, gc, cg);
    __syncthreads();
    load_tile_W128_16(j_w, cD, Ws, tid);
    __syncthreads();
    mma_loop64(Xh, Ws, wm, wn, gr, gc, cj);

#pragma unroll
    for (int i = 0; i < 2; i++)
#pragma unroll
        for (int j = 0; j < 8; j++) {
            int col = wn + j * 8 + 2 * gc;
            float ib0 = __ldg(&i_b[col]), ib1 = __ldg(&i_b[col + 1]);
            float jb0 = __ldg(&j_b[col]), jb1 = __ldg(&j_b[col + 1]);
#pragma unroll
            for (int half = 0; half < 2; half++) {
                int r = rowBase + wm + i * 16 + gr + half * 8;
                if (r >= cN) continue;
                int q0 = half * 2, q1 = half * 2 + 1;
                float2 o;
                o.x = sigmf(cg[i][j][q0] + ib0) * (cj[i][j][q0] + jb0);
                o.y = sigmf(cg[i][j][q1] + ib1) * (cj[i][j][q1] + jb1);
                *reinterpret_cast<float2*>(out + (size_t)r * cD + col) = o;
            }
        }
}

// ---------------- host ----------------
extern "C" void kernel_launch(void* const* d_in, const int* in_sizes, int n_in,
                              void* d_out, int out_size) {
    (void)in_sizes; (void)n_in; (void)out_size;
    const float* features = (const float*)d_in[0];
    const int*   src      = (const int*)d_in[1];
    const int*   dst      = (const int*)d_in[2];
    const int*   etypes   = (const int*)d_in[3];
    const float* W_et     = (const float*)d_in[4];
    const float* b_et     = (const float*)d_in[5];
    const float* W_ih     = (const float*)d_in[6];
    const float* b_ih     = (const float*)d_in[7];
    const float* W_hh     = (const float*)d_in[8];
    const float* b_hh     = (const float*)d_in[9];
    const float* i_w      = (const float*)d_in[10];
    const float* i_b      = (const float*)d_in[11];
    const float* j_w      = (const float*)d_in[12];
    const float* j_b      = (const float*)d_in[13];
    float* out = (float*)d_out;

    float *h0, *h1, *abuf;
    cudaGetSymbolAddress((void**)&h0, g_h0);
    cudaGetSymbolAddress((void**)&h1, g_h1);
    cudaGetSymbolAddress((void**)&abuf, g_a);

    cudaFuncSetAttribute(k_agg_etype, cudaFuncAttributeMaxDynamicSharedMemorySize, SM_AE);
    cudaFuncSetAttribute(k_gru_fused, cudaFuncAttributeMaxDynamicSharedMemorySize, SM_GRU);
    cudaFuncSetAttribute(k_head, cudaFuncAttributeMaxDynamicSharedMemorySize, SM_HEAD);

    // ---- CSR build (sorted by dst*4+etype) ----
    k_fill_deg<<<(cM + 255) / 256, 256>>>();
    k_hist<<<(cE + 255) / 256, 256>>>(dst, etypes);
    k_scan1<<<SCAN_NB, 1024>>>();
    k_scan2<<<1, 512>>>();
    k_scan3<<<SCAN_NB, 1024>>>();
    k_scatter<<<(cE + 255) / 256, 256>>>(src, dst, etypes);
    k_bsum<<<(cN * cD + 255) / 256, 256>>>(b_et);

    const int RB128 = (cN + 127) / 128;  // 782

    const float* hc = features;
    float* houts[3] = {h0, h1, h0};
    for (int s = 0; s < 3; s++) {
        k_agg_etype<<<RB128, 256, SM_AE>>>(hc, W_et);  // -> g_a
        k_gru_fused<<<RB128, 256, SM_GRU>>>(abuf, hc, W_ih, b_ih, W_hh, b_hh, houts[s]);
        hc = houts[s];
    }
    k_head<<<RB128, 256, SM_HEAD>>>(hc, features, i_w, i_b, j_w, j_b, out);
}